// round 7
// baseline (speedup 1.0000x reference)
#include <cuda_runtime.h>

// CRPS loss:
//   term1 = mean_i |s_i - y|                          (per pixel)
//   term2 = 0.5 * mean_{i,j} |s_i - s_j|              (per pixel)
//   out   = mean_pixels(term1 - term2)
//
// Key algebra: with v[] = sorted samples ascending,
//   sum_{i<j} |s_i - s_j| = sum_i (2i - 15) * v[i]     (N = 16)
// so term2*N^2/ (0.5*2) handled as: per-pixel = sum1/16 - sum2/256.

#define NS     16
#define PIXELS (4 * 1 * 256 * 256)   // 262144
#define TPB    256
#define NBLK   (PIXELS / TPB)        // 1024

__device__ float g_partial[NBLK];

__global__ void __launch_bounds__(TPB) crps_main_kernel(
    const float* __restrict__ samples,   // [16, PIXELS]
    const float* __restrict__ target)    // [PIXELS]
{
    const int pix = blockIdx.x * TPB + threadIdx.x;   // exact fit, no guard

    // Front-batched independent loads: MLP = 17 hides DRAM latency.
    float v[NS];
#pragma unroll
    for (int i = 0; i < NS; ++i)
        v[i] = samples[i * PIXELS + pix];
    const float y = target[pix];

    // term1 raw sum: FADD + FADD-with-|src| per sample (fma pipe).
    float sum1 = 0.0f;
#pragma unroll
    for (int i = 0; i < NS; ++i)
        sum1 += fabsf(v[i] - y);

    // Batcher odd-even mergesort, N=16: 63 compare-exchanges,
    // fully unrolled -> 126 FMNMX on the alu pipe, v[] stays in registers.
#pragma unroll
    for (int p = 1; p < NS; p <<= 1) {
#pragma unroll
        for (int k = p; k >= 1; k >>= 1) {
#pragma unroll
            for (int j = k % p; j + k < NS; j += 2 * k) {
#pragma unroll
                for (int i = 0; i < k; ++i) {
                    if (i + j + k < NS) {
                        if ((i + j) / (2 * p) == (i + j + k) / (2 * p)) {
                            float a  = v[i + j];
                            float b  = v[i + j + k];
                            v[i + j]     = fminf(a, b);
                            v[i + j + k] = fmaxf(a, b);
                        }
                    }
                }
            }
        }
    }

    // sum_{i<j}(v_j - v_i) via sorted weights: 16 FFMA-imm (rt=1).
    float sum2 = 0.0f;
#pragma unroll
    for (int i = 0; i < NS; ++i)
        sum2 = fmaf((float)(2 * i - 15), v[i], sum2);

    // per-pixel CRPS contribution
    float val = sum1 * (1.0f / 16.0f) - sum2 * (1.0f / 256.0f);

    // Deterministic block reduction (fixed-order shared tree).
    __shared__ float sh[TPB];
    sh[threadIdx.x] = val;
    __syncthreads();
#pragma unroll
    for (int s = TPB / 2; s > 0; s >>= 1) {
        if (threadIdx.x < s) sh[threadIdx.x] += sh[threadIdx.x + s];
        __syncthreads();
    }
    if (threadIdx.x == 0)
        g_partial[blockIdx.x] = sh[0];
}

__global__ void __launch_bounds__(TPB) crps_reduce_kernel(float* __restrict__ out)
{
    // 1024 partials, one block of 256: each thread sums 4 in fixed order.
    const int t = threadIdx.x;
    float a = g_partial[t] + g_partial[t + 256] +
              g_partial[t + 512] + g_partial[t + 768];

    __shared__ float sh[TPB];
    sh[t] = a;
    __syncthreads();
#pragma unroll
    for (int s = TPB / 2; s > 0; s >>= 1) {
        if (t < s) sh[t] += sh[t + s];
        __syncthreads();
    }
    if (t == 0)
        out[0] = sh[0] * (1.0f / (float)PIXELS);
}

extern "C" void kernel_launch(void* const* d_in, const int* in_sizes, int n_in,
                              void* d_out, int out_size)
{
    const float* samples = (const float*)d_in[0];
    const float* target  = (const float*)d_in[1];
    // Robustness: samples has 16x the elements of target; fix ordering if flipped.
    if (n_in >= 2 && in_sizes[0] < in_sizes[1]) {
        const float* tmp = samples; samples = target; target = tmp;
    }

    crps_main_kernel<<<NBLK, TPB>>>(samples, target);
    crps_reduce_kernel<<<1, TPB>>>((float*)d_out);
}

// round 8
// speedup vs baseline: 1.0090x; 1.0090x over previous
#include <cuda_runtime.h>

// CRPS loss, single fused kernel (last-block reduction):
//   term1 = mean_i |s_i - y|            per pixel
//   term2 = 0.5 * mean_{i,j} |s_i-s_j|  per pixel, via sorted-order identity:
//           sum_{i<j} |s_i - s_j| = sum_i (2i - 15) * v_sorted[i]   (N=16)
//   out   = mean over pixels of (sum1/16 - sum2/256)

#define NS     16
#define PIXELS (4 * 1 * 256 * 256)   // 262144
#define TPB    256
#define NBLK   (PIXELS / TPB)        // 1024

__device__ float        g_partial[NBLK];
__device__ unsigned int g_count;     // zero at load; last block resets to 0 each call

__global__ void __launch_bounds__(TPB) crps_fused_kernel(
    const float* __restrict__ samples,   // [16, PIXELS]
    const float* __restrict__ target,    // [PIXELS]
    float* __restrict__ out)
{
    const int tid = threadIdx.x;
    const int pix = blockIdx.x * TPB + tid;          // exact fit, no guard

    // Front-batched independent loads: MLP = 17 hides DRAM latency.
    float v[NS];
#pragma unroll
    for (int i = 0; i < NS; ++i)
        v[i] = samples[i * PIXELS + pix];
    const float y = target[pix];

    // term1 raw sum (fma pipe).
    float sum1 = 0.0f;
#pragma unroll
    for (int i = 0; i < NS; ++i)
        sum1 += fabsf(v[i] - y);

    // Batcher odd-even mergesort, N=16: 63 compare-exchanges -> 126 FMNMX (alu pipe).
#pragma unroll
    for (int p = 1; p < NS; p <<= 1) {
#pragma unroll
        for (int k = p; k >= 1; k >>= 1) {
#pragma unroll
            for (int j = k % p; j + k < NS; j += 2 * k) {
#pragma unroll
                for (int i = 0; i < k; ++i) {
                    if (i + j + k < NS) {
                        if ((i + j) / (2 * p) == (i + j + k) / (2 * p)) {
                            float a  = v[i + j];
                            float b  = v[i + j + k];
                            v[i + j]     = fminf(a, b);
                            v[i + j + k] = fmaxf(a, b);
                        }
                    }
                }
            }
        }
    }

    // sum_{i<j}(v_j - v_i) via sorted weights: 16 FFMA-imm (rt=1).
    float sum2 = 0.0f;
#pragma unroll
    for (int i = 0; i < NS; ++i)
        sum2 = fmaf((float)(2 * i - 15), v[i], sum2);

    float val = sum1 * (1.0f / 16.0f) - sum2 * (1.0f / 256.0f);

    // ── Block reduction: warp butterfly (fixed order -> deterministic) ──
#pragma unroll
    for (int m = 16; m >= 1; m >>= 1)
        val += __shfl_xor_sync(0xFFFFFFFFu, val, m);

    __shared__ float warp_sum[TPB / 32];             // 8 warps
    if ((tid & 31) == 0)
        warp_sum[tid >> 5] = val;
    __syncthreads();

    __shared__ volatile int s_last;
    if (tid == 0) {
        float bsum = 0.0f;
#pragma unroll
        for (int w = 0; w < TPB / 32; ++w)
            bsum += warp_sum[w];
        g_partial[blockIdx.x] = bsum;
        __threadfence();                             // partial visible before count bump
        unsigned int prev = atomicAdd(&g_count, 1u);
        s_last = (prev == (unsigned int)(NBLK - 1)) ? 1 : 0;
    }
    __syncthreads();

    // ── Last block: deterministic final reduction over all 1024 partials ──
    if (s_last) {
        // Each thread sums 4 partials in fixed index order (L2-hot, bypass L1).
        float a = __ldcg(&g_partial[tid])
                + __ldcg(&g_partial[tid + 256])
                + __ldcg(&g_partial[tid + 512])
                + __ldcg(&g_partial[tid + 768]);

        __shared__ float sh[TPB];
        sh[tid] = a;
        __syncthreads();
#pragma unroll
        for (int s = TPB / 2; s > 0; s >>= 1) {
            if (tid < s) sh[tid] += sh[tid + s];
            __syncthreads();
        }
        if (tid == 0) {
            out[0] = sh[0] * (1.0f / (float)PIXELS);
            g_count = 0;                             // restore invariant for next replay
        }
    }
}

extern "C" void kernel_launch(void* const* d_in, const int* in_sizes, int n_in,
                              void* d_out, int out_size)
{
    const float* samples = (const float*)d_in[0];
    const float* target  = (const float*)d_in[1];
    // Robustness: samples has 16x the elements of target; fix ordering if flipped.
    if (n_in >= 2 && in_sizes[0] < in_sizes[1]) {
        const float* tmp = samples; samples = target; target = tmp;
    }

    crps_fused_kernel<<<NBLK, TPB>>>(samples, target, (float*)d_out);
}